// round 16
// baseline (speedup 1.0000x reference)
#include <cuda_runtime.h>
#include <cuda_fp16.h>
#include <math.h>

constexpr int Bq   = 4;
constexpr int Nq   = 64;
constexpr int Fq   = 64;
constexpr int FINq = 32;
constexpr int EDIMq= 32;
constexpr int FFq  = Fq * Fq;          // 4096
constexpr int ROWS = Bq * Nq;          // 256 target rows (b,n)

constexpr int CHUNK_E = 4;             // edges per bulk chunk (32KB)
constexpr int NRING   = 2;             // double buffer

__device__ float  g_H[ROWS * Fq];
__device__ float  g_H2[ROWS * Fq];
__device__ float  g_agg1[ROWS * Fq];   // round-1 aggregates
__device__ int    g_done[ROWS / 2];    // per-row-pair completion counters
__device__ int    g_cnt[ROWS];
__device__ int    g_midx[ROWS * Nq];
// Interleaved: per slot 2048 half2; entry c (c = ii*64+j, ii<32) holds
// (A[ii][j], A[ii+32][j]).
__device__ __align__(16) __half2 g_Amat[(size_t)ROWS * Nq * (FFq / 2)];

__device__ __forceinline__ float sigm(float x) { return 1.0f / (1.0f + expf(-x)); }
__device__ __forceinline__ __half2 h2(unsigned int u) {
    return *reinterpret_cast<__half2*>(&u);
}
__device__ __forceinline__ unsigned long long pack2(float lo, float hi) {
    unsigned long long r;
    asm("mov.b64 %0, {%1, %2};" : "=l"(r) : "f"(lo), "f"(hi));
    return r;
}
__device__ __forceinline__ void unpack2(unsigned long long v, float& lo, float& hi) {
    asm("mov.b64 {%0, %1}, %2;" : "=f"(lo), "=f"(hi) : "l"(v));
}
__device__ __forceinline__ unsigned long long ffma2(
    unsigned long long a, unsigned long long b, unsigned long long c) {
    unsigned long long d;
    asm("fma.rn.f32x2 %0, %1, %2, %3;" : "=l"(d) : "l"(a), "l"(b), "l"(c));
    return d;
}
__device__ __forceinline__ unsigned smem_u32(const void* p) {
    return (unsigned)__cvta_generic_to_shared(p);
}
__device__ __forceinline__ void mbar_init(unsigned mbar, unsigned count) {
    asm volatile("mbarrier.init.shared.b64 [%0], %1;" :: "r"(mbar), "r"(count) : "memory");
}
__device__ __forceinline__ void mbar_expect_tx(unsigned mbar, unsigned bytes) {
    asm volatile("mbarrier.arrive.expect_tx.shared.b64 _, [%0], %1;"
                 :: "r"(mbar), "r"(bytes) : "memory");
}
__device__ __forceinline__ void mbar_wait(unsigned mbar, unsigned phase) {
    unsigned done;
    asm volatile(
        "{\n\t.reg .pred p;\n\t"
        "mbarrier.try_wait.parity.acquire.cta.shared::cta.b64 p, [%1], %2;\n\t"
        "selp.b32 %0, 1, 0, p;\n\t}"
        : "=r"(done) : "r"(mbar), "r"(phase) : "memory");
    if (!done) {
        asm volatile(
            "{\n\t.reg .pred P1;\n\t"
            "WL_%=:\n\t"
            "mbarrier.try_wait.parity.acquire.cta.shared::cta.b64 P1, [%0], %1, 0x989680;\n\t"
            "@P1 bra.uni WD_%=;\n\t"
            "bra.uni WL_%=;\n\t"
            "WD_%=:\n\t}"
            :: "r"(mbar), "r"(phase) : "memory");
    }
}
__device__ __forceinline__ void bulk_ld(unsigned dst_smem, const void* src,
                                        unsigned bytes, unsigned mbar) {
    asm volatile(
        "cp.async.bulk.shared::cta.global.mbarrier::complete_tx::bytes [%0], [%1], %2, [%3];"
        :: "r"(dst_smem), "l"(src), "r"(bytes), "r"(mbar) : "memory");
}

// ---------------------------------------------------------------------------
// Kernel 1: edge MLP + embedding + compaction + ROUND-1 agg + inline GRU.
// DYNAMIC smem layout (GRU scratch aliased into the dead Es2 region):
//   [0, 32768)       Es2  (128*32 ull)      | after MLP: GRU scratch
//   [32768, 49152)   Hs   (64x64 float)
//   [49152, 49664)   s_m  (128 int)
//   [49664, 49680)   s_cnt(2 int) + pad
//   [49680, 49808)   red  (32 float)
//   [49808, 49824)   s_last + pad
// ---------------------------------------------------------------------------
constexpr int E_ES2  = 0;
constexpr int E_HS   = 32768;
constexpr int E_SM   = 49152;
constexpr int E_CNT  = 49664;
constexpr int E_RED  = 49680;
constexpr int E_LAST = 49808;
constexpr int ESM_TOTAL = 49824;
// aliased (in Es2 region, used only after the MLP loop):
constexpr int E_GW   = 0;        // 384 floats (xg1|xg2)
constexpr int E_HGW  = 1536;     // 192 floats
constexpr int E_H1   = 2304;     // 64 floats
constexpr int E_AGGV = 2560;     // 64 floats
constexpr int E_XOLD = 2816;     // 64 floats

__global__ __launch_bounds__(256) void k_edge(
    const float* __restrict__ A, const float* __restrict__ E,
    const float* __restrict__ X,
    const float* __restrict__ W_embed, const float* __restrict__ b_embed,
    const float* __restrict__ W_edge, const float* __restrict__ b_edge,
    const float* __restrict__ gk, const float* __restrict__ grk,
    const float* __restrict__ gb, const float* __restrict__ grb)
{
    extern __shared__ __align__(16) char smem[];
    unsigned long long* Es2 = reinterpret_cast<unsigned long long*>(smem + E_ES2);
    float (*Hs)[Fq] = reinterpret_cast<float(*)[Fq]>(smem + E_HS);
    int*   s_m   = reinterpret_cast<int*>(smem + E_SM);
    int*   s_cnt = reinterpret_cast<int*>(smem + E_CNT);
    float* red   = reinterpret_cast<float*>(smem + E_RED);
    int*   s_lastp = reinterpret_cast<int*>(smem + E_LAST);
    float* gw    = reinterpret_cast<float*>(smem + E_GW);
    float* hgw   = reinterpret_cast<float*>(smem + E_HGW);
    float* h1v   = reinterpret_cast<float*>(smem + E_H1);
    float* aggv  = reinterpret_cast<float*>(smem + E_AGGV);
    float* xoldv = reinterpret_cast<float*>(smem + E_XOLD);

    int rp = blockIdx.x, by = blockIdx.y, c0 = by * 256, t = threadIdx.x;
    int b = (rp * 2) >> 6;

    // ---- compaction (warps 0-1) ----
    if (t < 64) {
        int r = t >> 5, lane = t & 31;
        int row = rp * 2 + r;
        const float* Arow = A + (size_t)row * Nq;
        unsigned a0 = (Arow[lane] > 0.5f) ? 1u : 0u;
        unsigned a1 = (Arow[32 + lane] > 0.5f) ? 1u : 0u;
        unsigned m0 = __ballot_sync(0xffffffffu, a0);
        unsigned m1 = __ballot_sync(0xffffffffu, a1);
        unsigned lm = (lane == 0) ? 0u : (0xffffffffu >> (32 - lane));
        int n0 = __popc(m0);
        if (a0) { int p = __popc(m0 & lm); s_m[r * 64 + p] = lane;
                  if (by == 0) g_midx[row * Nq + p] = lane; }
        if (a1) { int p = n0 + __popc(m1 & lm); s_m[r * 64 + p] = 32 + lane;
                  if (by == 0) g_midx[row * Nq + p] = 32 + lane; }
        if (lane == 0) { int c = n0 + __popc(m1); s_cnt[r] = c;
                         if (by == 0) g_cnt[row] = c; }
    }

    // ---- local embedding of ALL 64 batch nodes ----
    for (int idx = t; idx < Nq * Fq; idx += 256) {
        int m = idx >> 6, f = idx & 63;
        float acc = b_embed[f];
#pragma unroll
        for (int k = 0; k < FINq; k++)
            acc += X[((size_t)b * Nq + m) * FINq + k] * W_embed[k * Fq + f];
        Hs[m][f] = fmaxf(acc, 0.0f);
    }
    __syncthreads();
    int cnt0 = s_cnt[0], ne = cnt0 + s_cnt[1];

    for (int i = t; i < ne * EDIMq; i += 256) {
        int kk = i >> 5, e = i & 31;
        int p  = (kk >= cnt0) ? 1 : 0;
        int kl = kk - (p ? cnt0 : 0);
        int row = rp * 2 + p;
        int m  = s_m[p * 64 + kl];
        float v = E[((size_t)row * Nq + m) * EDIMq + e];
        Es2[kk * EDIMq + e] = pack2(v, v);
    }
    __syncthreads();

    // ---- MLP hot loop (R14-identical) ----
    int c_a = c0 + t, c_b = c_a + 2048;
    unsigned long long w01[EDIMq];
#pragma unroll
    for (int e = 0; e < EDIMq; e++)
        w01[e] = pack2(W_edge[(size_t)e * FFq + c_a], W_edge[(size_t)e * FFq + c_b]);
    unsigned long long bias01 = pack2(b_edge[c_a], b_edge[c_b]);

    auto emit = [&](int kk, unsigned long long acc) {
        float a0, a1;
        unpack2(acc, a0, a1);
        int p  = (kk >= cnt0) ? 1 : 0;
        int kl = kk - (p ? cnt0 : 0);
        size_t slot = (size_t)(rp * 2 + p) * Nq + kl;
        g_Amat[slot * (FFq / 2) + c_a] =
            __floats2half2_rn(fmaxf(a0, 0.0f), fmaxf(a1, 0.0f));
    };

    int kk = 0;
    for (; kk + 2 <= ne; kk += 2) {
        unsigned long long acc0 = bias01, acc1 = bias01;
#pragma unroll
        for (int e = 0; e < EDIMq; e++) {
            acc0 = ffma2(Es2[kk * EDIMq + e],       w01[e], acc0);
            acc1 = ffma2(Es2[(kk + 1) * EDIMq + e], w01[e], acc1);
        }
        emit(kk, acc0);
        emit(kk + 1, acc1);
    }
    if (kk < ne) {
        unsigned long long acc0 = bias01;
#pragma unroll
        for (int e = 0; e < EDIMq; e++)
            acc0 = ffma2(Es2[kk * EDIMq + e], w01[e], acc0);
        emit(kk, acc0);
    }

    // ---- round-1 aggregation: re-read own L2-hot columns, dot with Hs ----
    int j = t & 63;
    float r0lo = 0.0f, r0hi = 0.0f, r1lo = 0.0f, r1hi = 0.0f;
    {
        const unsigned* Au = reinterpret_cast<const unsigned*>(g_Amat);
        for (int k2 = 0; k2 < ne; k2++) {
            int p  = (k2 >= cnt0) ? 1 : 0;
            int kl = k2 - (p ? cnt0 : 0);
            size_t slot = (size_t)(rp * 2 + p) * Nq + kl;
            unsigned av = __ldcg(&Au[slot * (FFq / 2) + c_a]);
            float2 f2 = __half22float2(h2(av));
            float h = Hs[s_m[p * 64 + kl]][j];
            if (p == 0) { r0lo += f2.x * h; r0hi += f2.y * h; }
            else        { r1lo += f2.x * h; r1hi += f2.y * h; }
        }
    }
#pragma unroll
    for (int ofs = 16; ofs > 0; ofs >>= 1) {
        r0lo += __shfl_xor_sync(0xffffffffu, r0lo, ofs);
        r0hi += __shfl_xor_sync(0xffffffffu, r0hi, ofs);
        r1lo += __shfl_xor_sync(0xffffffffu, r1lo, ofs);
        r1hi += __shfl_xor_sync(0xffffffffu, r1hi, ofs);
    }
    int wid = t >> 5;
    if ((t & 31) == 0) {
        red[wid * 4 + 0] = r0lo; red[wid * 4 + 1] = r0hi;
        red[wid * 4 + 2] = r1lo; red[wid * 4 + 3] = r1hi;
    }
    __syncthreads();
    if ((t & 63) == 0) {
        int g = t >> 6;
        int ii = by * 4 + g;
        g_agg1[(size_t)(rp * 2)     * Fq + ii]      = red[2*g*4+0] + red[(2*g+1)*4+0];
        g_agg1[(size_t)(rp * 2)     * Fq + ii + 32] = red[2*g*4+1] + red[(2*g+1)*4+1];
        g_agg1[(size_t)(rp * 2 + 1) * Fq + ii]      = red[2*g*4+2] + red[(2*g+1)*4+2];
        g_agg1[(size_t)(rp * 2 + 1) * Fq + ii + 32] = red[2*g*4+3] + red[(2*g+1)*4+3];
    }

    // ---- last of 8 blocks for this row-pair runs the round-1 GRU ----
    __threadfence();
    __syncthreads();
    if (t == 0) {
        int old = atomicAdd(&g_done[rp], 1);
        *s_lastp = (old == 7);
        if (*s_lastp) { g_done[rp] = 0; __threadfence(); }
    }
    __syncthreads();
    if (!*s_lastp) return;

    for (int r2 = 0; r2 < 2; r2++) {
        int row = rp * 2 + r2;
        if (t < 64) {
            xoldv[t] = Hs[(row & 63)][t];
            aggv[t]  = __ldcg(&g_agg1[(size_t)row * Fq + t]);
        }
        __syncthreads();
        if (t < 192) {
            float a1 = gb[t], a2 = gb[t];
#pragma unroll 8
            for (int jj = 0; jj < Fq; jj++) {
                float w = gk[jj * 192 + t];
                a1 += xoldv[jj] * w;
                a2 += aggv[jj] * w;
            }
            gw[t] = a1;
            gw[192 + t] = a2;
        }
        __syncthreads();
        if (t < Fq) {
            float z = sigm(gw[t] + grb[t]);
            float rr = sigm(gw[Fq + t] + grb[Fq + t]);
            float cand = tanhf(gw[2 * Fq + t] + rr * grb[2 * Fq + t]);
            h1v[t] = (1.0f - z) * cand;
        }
        __syncthreads();
        if (t < 192) {
            float hh = grb[t];
#pragma unroll 8
            for (int jj = 0; jj < Fq; jj++) hh += h1v[jj] * grk[jj * 192 + t];
            hgw[t] = hh;
        }
        __syncthreads();
        if (t < Fq) {
            float z = sigm(gw[192 + t] + hgw[t]);
            float rr = sigm(gw[192 + Fq + t] + hgw[Fq + t]);
            float cand = tanhf(gw[192 + 2 * Fq + t] + rr * hgw[2 * Fq + t]);
            g_H2[(size_t)row * Fq + t] = z * h1v[t] + (1.0f - z) * cand;
        }
        __syncthreads();
    }
}

// ---------------------------------------------------------------------------
// Kernel 2: one full round (rounds 2 & 3). R14 TMA-bulk version, verbatim.
// ---------------------------------------------------------------------------
constexpr int RING_OFF = 0;
constexpr int HS_OFF   = NRING * CHUNK_E * 8192;     // 65536
constexpr int FLT_OFF  = HS_OFF + Nq * Fq * 4;
constexpr int MB_OFF   = FLT_OFF + 768 * 4;
constexpr int KSM_TOTAL= MB_OFF + 64;

__global__ __launch_bounds__(512) void k_round(
    const float* __restrict__ Hin, float* __restrict__ Hout,
    const float* __restrict__ gk, const float* __restrict__ grk,
    const float* __restrict__ gb, const float* __restrict__ grb)
{
    extern __shared__ __align__(16) char smem[];
    char*    ring = smem + RING_OFF;
    __half2* hs2  = reinterpret_cast<__half2*>(smem + HS_OFF);
    float*   fl   = reinterpret_cast<float*>(smem + FLT_OFF);
    float* xold = fl;
    float* aggv = fl + 64;
    float* h1   = fl + 128;
    float* xg1  = fl + 192;
    float* xg2  = fl + 384;
    float* hg2  = fl + 576;
    unsigned mb0 = smem_u32(smem + MB_OFF);

    int row = blockIdx.x;
    int b = row >> 6;
    int t = threadIdx.x;
    int q = t & 15;

    int cnt = g_cnt[row];
    int nchunk = (cnt + CHUNK_E - 1) / CHUNK_E;
    const char* Asrc = reinterpret_cast<const char*>(g_Amat)
                     + (size_t)row * Nq * 8192;

    auto issue = [&](int c) {
        int s = c & 1;
        int e0 = c * CHUNK_E;
        unsigned bytes = (unsigned)(min(CHUNK_E, cnt - e0) * 8192);
        mbar_expect_tx(mb0 + s * 8, bytes);
        bulk_ld(smem_u32(ring + s * (CHUNK_E * 8192)), Asrc + (size_t)e0 * 8192,
                bytes, mb0 + s * 8);
    };

    if (t == 0) {
        mbar_init(mb0, 1);
        mbar_init(mb0 + 8, 1);
        asm volatile("fence.proxy.async.shared::cta;" ::: "memory");
        if (nchunk > 0) issue(0);
        if (nchunk > 1) issue(1);
    }

    __syncthreads();
    for (int idx = t; idx < cnt * Fq; idx += 512) {
        int e = idx >> 6, j = idx & 63;
        int m = g_midx[row * Nq + e];
        hs2[e * Fq + j] = __float2half2_rn(Hin[((size_t)b * Nq + m) * Fq + j]);
    }
    if (t >= 448) xold[t - 448] = Hin[(size_t)row * Fq + (t - 448)];
    __syncthreads();

    float flo = 0.0f, fhi = 0.0f;
    for (int c = 0; c < nchunk; c++) {
        int s = c & 1;
        mbar_wait(mb0 + s * 8, (c >> 1) & 1);
        int e0 = c * CHUNK_E;
        int nE = min(CHUNK_E, cnt - e0);
        const char* base = ring + s * (CHUNK_E * 8192);
#pragma unroll
        for (int el = 0; el < CHUNK_E; el++) {
            if (el < nE) {
                uint4 a  = *reinterpret_cast<const uint4*>(base + el * 8192 + t * 16);
                uint4 hv = *reinterpret_cast<const uint4*>(hs2 + (e0 + el) * Fq + q * 4);
                __half2 c2 = __hmul2(h2(a.x), h2(hv.x));
                c2 = __hfma2(h2(a.y), h2(hv.y), c2);
                c2 = __hfma2(h2(a.z), h2(hv.z), c2);
                c2 = __hfma2(h2(a.w), h2(hv.w), c2);
                float2 f = __half22float2(c2);
                flo += f.x;
                fhi += f.y;
            }
        }
        __syncthreads();
        if (t == 0 && c + NRING < nchunk) issue(c + NRING);
    }

    flo += __shfl_xor_sync(0xffffffffu, flo, 1);
    flo += __shfl_xor_sync(0xffffffffu, flo, 2);
    flo += __shfl_xor_sync(0xffffffffu, flo, 4);
    flo += __shfl_xor_sync(0xffffffffu, flo, 8);
    fhi += __shfl_xor_sync(0xffffffffu, fhi, 1);
    fhi += __shfl_xor_sync(0xffffffffu, fhi, 2);
    fhi += __shfl_xor_sync(0xffffffffu, fhi, 4);
    fhi += __shfl_xor_sync(0xffffffffu, fhi, 8);
    if (q == 0) {
        int ii = t >> 4;
        aggv[ii]      = flo;
        aggv[ii + 32] = fhi;
    }
    __syncthreads();

    if (t < 192) {
        float a1 = gb[t], a2 = gb[t];
#pragma unroll 8
        for (int j = 0; j < Fq; j++) {
            float w = gk[j * 192 + t];
            a1 += xold[j] * w;
            a2 += aggv[j] * w;
        }
        xg1[t] = a1;
        xg2[t] = a2;
    }
    __syncthreads();
    if (t < Fq) {
        float z = sigm(xg1[t] + grb[t]);
        float rr = sigm(xg1[Fq + t] + grb[Fq + t]);
        float cand = tanhf(xg1[2 * Fq + t] + rr * grb[2 * Fq + t]);
        h1[t] = (1.0f - z) * cand;
    }
    __syncthreads();
    if (t < 192) {
        float hh = grb[t];
#pragma unroll 8
        for (int j = 0; j < Fq; j++) hh += h1[j] * grk[j * 192 + t];
        hg2[t] = hh;
    }
    __syncthreads();
    if (t < Fq) {
        float z = sigm(xg2[t] + hg2[t]);
        float rr = sigm(xg2[Fq + t] + hg2[Fq + t]);
        float cand = tanhf(xg2[2 * Fq + t] + rr * hg2[2 * Fq + t]);
        Hout[(size_t)row * Fq + t] = z * h1[t] + (1.0f - z) * cand;
    }
}

// ---------------------------------------------------------------------------
extern "C" void kernel_launch(void* const* d_in, const int* in_sizes, int n_in,
                              void* d_out, int out_size)
{
    const float* X       = (const float*)d_in[0];
    const float* A       = (const float*)d_in[1];
    const float* E       = (const float*)d_in[2];
    const float* W_embed = (const float*)d_in[3];
    const float* b_embed = (const float*)d_in[4];
    const float* W_edge  = (const float*)d_in[5];
    const float* b_edge  = (const float*)d_in[6];
    const float* gk      = (const float*)d_in[7];
    const float* grk     = (const float*)d_in[8];
    const float* gb      = (const float*)d_in[9];
    const float* grb     = (const float*)d_in[10];
    float* out = (float*)d_out;

    float *hbuf = nullptr, *h2buf = nullptr;
    cudaGetSymbolAddress((void**)&hbuf, g_H);
    cudaGetSymbolAddress((void**)&h2buf, g_H2);

    static bool attr_set = false;
    if (!attr_set) {
        cudaFuncSetAttribute(k_round, cudaFuncAttributeMaxDynamicSharedMemorySize,
                             KSM_TOTAL);
        cudaFuncSetAttribute(k_edge, cudaFuncAttributeMaxDynamicSharedMemorySize,
                             ESM_TOTAL);
        attr_set = true;
    }

    // edge MLP + embed + compaction + ROUND 1 (agg + GRU inline) -> g_H2
    k_edge<<<dim3(ROWS / 2, 8), 256, ESM_TOTAL>>>(A, E, X, W_embed, b_embed,
                                                  W_edge, b_edge, gk, grk, gb, grb);
    // rounds 2 and 3
    k_round<<<ROWS, 512, KSM_TOTAL>>>(h2buf, hbuf, gk, grk, gb, grb);
    k_round<<<ROWS, 512, KSM_TOTAL>>>(hbuf,  out,  gk, grk, gb, grb);
}